// round 1
// baseline (speedup 1.0000x reference)
#include <cuda_runtime.h>
#include <cstdint>
#include <cstddef>

#define N_CAM 6
#define C_CH  128
#define H_IMG 64
#define W_IMG 176
#define HW    (H_IMG * W_IMG)     // 11264
#define NQ    640000              // 200*200*16

// Scratch: img_feats transposed to (cam, h, w, c) so a query's 128 channels
// are 512 contiguous bytes. 34.6 MB — static __device__ array (alloc-free).
__device__ float g_scratch[(size_t)N_CAM * HW * C_CH];
__device__ int   g_valid_is_byte;

// ---------------------------------------------------------------------------
// Detect element size of `valid`. Bool stored as 1 byte has ~30% nonzero bytes
// at offsets ≡ 1 (mod 4); int32(0/1) and float32(0.0/1.0) have 0x00 there.
// ---------------------------------------------------------------------------
__global__ void detect_kernel(const unsigned char* __restrict__ vb) {
    __shared__ int any;
    if (threadIdx.x == 0) any = 0;
    __syncthreads();
    int found = 0;
    for (int i = threadIdx.x; i < 1024; i += blockDim.x)
        if (vb[1 + 4 * i] != 0) found = 1;
    if (found) atomicOr(&any, 1);
    __syncthreads();
    if (threadIdx.x == 0) g_valid_is_byte = any;
}

// ---------------------------------------------------------------------------
// Tiled transpose per cam: (C, HW) -> (HW, C). 32x32 tiles, smem pad 33.
// Both global read and write fully coalesced.
// ---------------------------------------------------------------------------
__global__ __launch_bounds__(256) void transpose_kernel(const float* __restrict__ img) {
    __shared__ float tile[32][33];
    const int cam = blockIdx.z;
    const int hw0 = blockIdx.x * 32;
    const int c0  = blockIdx.y * 32;
    const int tx = threadIdx.x, ty = threadIdx.y;   // 32 x 8

    const float* src = img + (size_t)cam * C_CH * HW;
    float*       dst = g_scratch + (size_t)cam * HW * C_CH;

#pragma unroll
    for (int k = 0; k < 4; k++) {
        int c = c0 + ty + k * 8;
        tile[ty + k * 8][tx] = src[(size_t)c * HW + hw0 + tx];
    }
    __syncthreads();
#pragma unroll
    for (int k = 0; k < 4; k++) {
        int hw = hw0 + ty + k * 8;
        dst[(size_t)hw * C_CH + c0 + tx] = tile[tx][ty + k * 8];
    }
}

// ---------------------------------------------------------------------------
// Gather: block handles 32 queries x 128 channels.
// Phase A: warp-per-query, coalesced 128B gathers from g_scratch into smem
//          tile [t][c] padded to 129 (conflict-free STS: banks (t + c) % 32).
// Phase B: write out[c*NQ + q] with lanes covering consecutive q -> each
//          warp STG is 128B contiguous; LDS stride 129 -> conflict-free.
// ---------------------------------------------------------------------------
__global__ __launch_bounds__(256) void gather_kernel(
    const float* __restrict__ pts,
    const void*  __restrict__ valid,
    float*       __restrict__ out)
{
    __shared__ float sm[32 * 129];
    const int tid = threadIdx.x;
    const int w = tid >> 5, l = tid & 31;
    const int q0 = blockIdx.x * 32;

    const int isByte = g_valid_is_byte;
    const unsigned char* vb = (const unsigned char*)valid;
    const unsigned int*  vw = (const unsigned int*)valid;

#pragma unroll
    for (int i = 0; i < 4; i++) {
        const int t = w * 4 + i;
        const int q = q0 + t;

        // sel = highest cam index with valid[cam][q]
        int cam = -1;
#pragma unroll
        for (int cc = N_CAM - 1; cc >= 0; cc--) {
            bool v = isByte ? (vb[(size_t)cc * NQ + q] != 0)
                            : (vw[(size_t)cc * NQ + q] != 0);
            if (v) { cam = cc; break; }
        }

        if (cam >= 0) {
            float2 p = ((const float2*)pts)[(size_t)cam * NQ + q];
            int x = __float2int_rn(p.x);   // round-half-to-even == jnp.round
            int y = __float2int_rn(p.y);
            x = min(max(x, 0), W_IMG - 1);
            y = min(max(y, 0), H_IMG - 1);
            const float* base =
                g_scratch + ((size_t)cam * HW + (size_t)y * W_IMG + x) * C_CH;
#pragma unroll
            for (int k = 0; k < 4; k++)
                sm[t * 129 + l + 32 * k] = base[l + 32 * k];
        } else {
#pragma unroll
            for (int k = 0; k < 4; k++)
                sm[t * 129 + l + 32 * k] = 0.0f;
        }
    }
    __syncthreads();

#pragma unroll
    for (int j = 0; j < 16; j++) {
        const int c = w * 16 + j;
        out[(size_t)c * NQ + q0 + l] = sm[l * 129 + c];
    }
}

// ---------------------------------------------------------------------------
extern "C" void kernel_launch(void* const* d_in, const int* in_sizes, int n_in,
                              void* d_out, int out_size) {
    const float* img   = (const float*)d_in[0];   // (6,128,64,176) f32
    const float* pts   = (const float*)d_in[1];   // (6,640000,2)  f32
    const void*  valid = d_in[2];                 // (6,640000) bool-ish
    float*       out   = (float*)d_out;           // (128,200,200,16) f32

    detect_kernel<<<1, 256>>>((const unsigned char*)valid);

    dim3 tb(32, 8);
    dim3 tg(HW / 32, C_CH / 32, N_CAM);           // (352, 4, 6)
    transpose_kernel<<<tg, tb>>>(img);

    gather_kernel<<<NQ / 32, 256>>>(pts, valid, out);
}

// round 3
// speedup vs baseline: 1.1710x; 1.1710x over previous
#include <cuda_runtime.h>
#include <cstdint>
#include <cstddef>

#define N_CAM 6
#define C_CH  128
#define H_IMG 64
#define W_IMG 176
#define HW    (H_IMG * W_IMG)     // 11264
#define NQ    640000              // 200*200*16

// Scratch: img_feats transposed to (cam, h, w, c) so a query's 128 channels
// are 512 contiguous bytes. 34.6 MB — static __device__ array (alloc-free).
__device__ float g_scratch[(size_t)N_CAM * HW * C_CH];
__device__ int   g_valid_is_byte;

// ---- cache-hinted accessors (createpolicy + L2::cache_hint form: the only
// encoding ptxas/sm_103a accepts for sub-256-bit accesses) -------------------
__device__ __forceinline__ unsigned long long policy_evict_last() {
    unsigned long long p;
    asm("createpolicy.fractional.L2::evict_last.b64 %0, 1.0;" : "=l"(p));
    return p;
}
__device__ __forceinline__ float ldg_el(const float* ptr, unsigned long long pol) {
    float v;
    asm volatile("ld.global.L2::cache_hint.f32 %0, [%1], %2;"
                 : "=f"(v) : "l"(ptr), "l"(pol));
    return v;
}
__device__ __forceinline__ void stg_el(float* ptr, float v, unsigned long long pol) {
    asm volatile("st.global.L2::cache_hint.f32 [%0], %1, %2;"
                 :: "l"(ptr), "f"(v), "l"(pol));
}

// ---------------------------------------------------------------------------
// Tiled transpose per cam: (C, HW) -> (HW, C). 32x32 tiles, smem pad 33.
// Reads are streaming (__ldcs); scratch writes pinned via evict_last hint.
// Block (0,0,0) warp 0 additionally detects the element size of `valid`:
// a 1-byte bool array has ~30% nonzero bytes at offsets ≡ 1 (mod 4);
// int32/float32 encodings of 0/1 have 0x00 there. P(false negative) ~ 0.7^1024.
// ---------------------------------------------------------------------------
__global__ __launch_bounds__(256) void transpose_kernel(
    const float* __restrict__ img, const unsigned char* __restrict__ vb)
{
    __shared__ float tile[32][33];
    const int cam = blockIdx.z;
    const int hw0 = blockIdx.x * 32;
    const int c0  = blockIdx.y * 32;
    const int tx = threadIdx.x, ty = threadIdx.y;   // 32 x 8

    if (blockIdx.x == 0 && blockIdx.y == 0 && blockIdx.z == 0 && ty == 0) {
        int found = 0;
        for (int i = tx; i < 1024; i += 32)
            if (vb[1 + 4 * i] != 0) found = 1;
        unsigned m = __ballot_sync(0xffffffffu, found);
        if (tx == 0) g_valid_is_byte = (m != 0u) ? 1 : 0;
    }

    const unsigned long long pol = policy_evict_last();
    const float* src = img + (size_t)cam * C_CH * HW;
    float*       dst = g_scratch + (size_t)cam * HW * C_CH;

#pragma unroll
    for (int k = 0; k < 4; k++) {
        int c = c0 + ty + k * 8;
        tile[ty + k * 8][tx] = __ldcs(&src[(size_t)c * HW + hw0 + tx]);
    }
    __syncthreads();
#pragma unroll
    for (int k = 0; k < 4; k++) {
        int hw = hw0 + ty + k * 8;
        stg_el(&dst[(size_t)hw * C_CH + c0 + tx], tile[tx][ty + k * 8], pol);
    }
}

// ---------------------------------------------------------------------------
// Gather: block handles 32 queries x 128 channels.
// Phase A: warp-per-query, coalesced 128B gathers (evict_last hint — keep
//          scratch L2-resident) into smem tile [t][c] pad 129 (conflict-free).
// Phase B: out[c*NQ + q] written with __stcs (evict-first — don't let the
//          328MB output stream evict the scratch). 128B contiguous per STG.
// ---------------------------------------------------------------------------
__global__ __launch_bounds__(256) void gather_kernel(
    const float* __restrict__ pts,
    const void*  __restrict__ valid,
    float*       __restrict__ out)
{
    __shared__ float sm[32 * 129];
    const int tid = threadIdx.x;
    const int w = tid >> 5, l = tid & 31;
    const int q0 = blockIdx.x * 32;

    const unsigned long long pol = policy_evict_last();
    const int isByte = g_valid_is_byte;
    const unsigned char* vb = (const unsigned char*)valid;
    const unsigned int*  vw = (const unsigned int*)valid;

#pragma unroll
    for (int i = 0; i < 4; i++) {
        const int t = w * 4 + i;
        const int q = q0 + t;

        // Branchless: load all 6 valid flags (batched, high MLP), select max cam.
        bool v[N_CAM];
        if (isByte) {
#pragma unroll
            for (int cc = 0; cc < N_CAM; cc++) v[cc] = vb[(size_t)cc * NQ + q] != 0;
        } else {
#pragma unroll
            for (int cc = 0; cc < N_CAM; cc++) v[cc] = vw[(size_t)cc * NQ + q] != 0u;
        }
        int cam = -1;
#pragma unroll
        for (int cc = 0; cc < N_CAM; cc++) cam = v[cc] ? cc : cam;

        if (cam >= 0) {
            float2 p = ((const float2*)pts)[(size_t)cam * NQ + q];
            int x = __float2int_rn(p.x);   // round-half-to-even == jnp.round
            int y = __float2int_rn(p.y);
            x = min(max(x, 0), W_IMG - 1);
            y = min(max(y, 0), H_IMG - 1);
            const float* base =
                g_scratch + ((size_t)cam * HW + (size_t)y * W_IMG + x) * C_CH;
#pragma unroll
            for (int k = 0; k < 4; k++)
                sm[t * 129 + l + 32 * k] = ldg_el(&base[l + 32 * k], pol);
        } else {
#pragma unroll
            for (int k = 0; k < 4; k++)
                sm[t * 129 + l + 32 * k] = 0.0f;
        }
    }
    __syncthreads();

#pragma unroll
    for (int j = 0; j < 16; j++) {
        const int c = w * 16 + j;
        __stcs(&out[(size_t)c * NQ + q0 + l], sm[l * 129 + c]);
    }
}

// ---------------------------------------------------------------------------
extern "C" void kernel_launch(void* const* d_in, const int* in_sizes, int n_in,
                              void* d_out, int out_size) {
    const float* img   = (const float*)d_in[0];   // (6,128,64,176) f32
    const float* pts   = (const float*)d_in[1];   // (6,640000,2)  f32
    const void*  valid = d_in[2];                 // (6,640000) bool-ish
    float*       out   = (float*)d_out;           // (128,200,200,16) f32

    dim3 tb(32, 8);
    dim3 tg(HW / 32, C_CH / 32, N_CAM);           // (352, 4, 6)
    transpose_kernel<<<tg, tb>>>(img, (const unsigned char*)valid);

    gather_kernel<<<NQ / 32, 256>>>(pts, valid, out);
}

// round 4
// speedup vs baseline: 1.6092x; 1.3742x over previous
#include <cuda_runtime.h>
#include <cstdint>
#include <cstddef>

#define N_CAM 6
#define C_CH  128
#define H_IMG 64
#define W_IMG 176
#define HW    (H_IMG * W_IMG)     // 11264
#define NQ    640000              // 200*200*16

// Scratch: img_feats transposed to (cam, h, w, c): query's 128 channels are
// 512 contiguous bytes. 34.6 MB static __device__ (alloc-free).
__device__ float g_scratch[(size_t)N_CAM * HW * C_CH];
// Per-query packed spatial index into scratch (element-row index), -1 invalid.
__device__ int g_idx[NQ];

// ---- cache-hinted accessors (createpolicy + L2::cache_hint) ----------------
__device__ __forceinline__ unsigned long long policy_evict_last() {
    unsigned long long p;
    asm("createpolicy.fractional.L2::evict_last.b64 %0, 1.0;" : "=l"(p));
    return p;
}
__device__ __forceinline__ void stg_el(float* ptr, float v, unsigned long long pol) {
    asm volatile("st.global.L2::cache_hint.f32 [%0], %1, %2;"
                 :: "l"(ptr), "f"(v), "l"(pol));
}
__device__ __forceinline__ float4 ldg_el4(const float4* ptr, unsigned long long pol) {
    float4 v;
    asm volatile("ld.global.L2::cache_hint.v4.f32 {%0,%1,%2,%3}, [%4], %5;"
                 : "=f"(v.x), "=f"(v.y), "=f"(v.z), "=f"(v.w)
                 : "l"(ptr), "l"(pol));
    return v;
}

// ---------------------------------------------------------------------------
// Tiled transpose per cam: (C, HW) -> (HW, C). Streaming reads; scratch writes
// pinned in L2 via evict_last so the gather's re-reads stay L2-resident.
// ---------------------------------------------------------------------------
__global__ __launch_bounds__(256) void transpose_kernel(const float* __restrict__ img)
{
    __shared__ float tile[32][33];
    const int cam = blockIdx.z;
    const int hw0 = blockIdx.x * 32;
    const int c0  = blockIdx.y * 32;
    const int tx = threadIdx.x, ty = threadIdx.y;   // 32 x 8

    const unsigned long long pol = policy_evict_last();
    const float* src = img + (size_t)cam * C_CH * HW;
    float*       dst = g_scratch + (size_t)cam * HW * C_CH;

#pragma unroll
    for (int k = 0; k < 4; k++) {
        int c = c0 + ty + k * 8;
        tile[ty + k * 8][tx] = __ldcs(&src[(size_t)c * HW + hw0 + tx]);
    }
    __syncthreads();
#pragma unroll
    for (int k = 0; k < 4; k++) {
        int hw = hw0 + ty + k * 8;
        stg_el(&dst[(size_t)hw * C_CH + c0 + tx], tile[tx][ty + k * 8], pol);
    }
}

// ---------------------------------------------------------------------------
// Index precompute: 1 thread per query. Coalesced valid loads, max-cam select,
// round-to-nearest-even (== jnp.round), packed scratch row index (-1 invalid).
// Valid dtype detected per block: a 1-byte bool array has ~30% nonzero bytes
// at offsets ≡ 1 (mod 4); int32/f32 encodings of 0/1 have 0x00 there.
// 1024 samples -> P(false negative) ~ 0.7^1024.
// ---------------------------------------------------------------------------
__global__ __launch_bounds__(256) void index_kernel(
    const float* __restrict__ pts, const void* __restrict__ valid)
{
    const int tid = threadIdx.x;
    const int q = blockIdx.x * 256 + tid;
    const unsigned char* vb = (const unsigned char*)valid;
    const unsigned int*  vw = (const unsigned int*)valid;

    int found = 0;
#pragma unroll
    for (int j = 0; j < 4; j++)
        if (vb[1 + 4 * (tid * 4 + j)] != 0) found = 1;
    const int isByte = __syncthreads_or(found);

    int cam = -1;
    if (isByte) {
#pragma unroll
        for (int cc = 0; cc < N_CAM; cc++)
            if (vb[(size_t)cc * NQ + q] != 0) cam = cc;
    } else {
#pragma unroll
        for (int cc = 0; cc < N_CAM; cc++)
            if (vw[(size_t)cc * NQ + q] != 0u) cam = cc;
    }

    int p = -1;
    if (cam >= 0) {
        float2 pt = ((const float2*)pts)[(size_t)cam * NQ + q];
        int x = min(max(__float2int_rn(pt.x), 0), W_IMG - 1);
        int y = min(max(__float2int_rn(pt.y), 0), H_IMG - 1);
        p = cam * HW + y * W_IMG + x;
    }
    g_idx[q] = p;
}

// ---------------------------------------------------------------------------
// Gather: tile = 64 queries x 128 channels, 32KB smem, all 128-bit accesses.
// XOR-swizzled float4 layout: slot(q, f4) = q*32 + (f4 ^ (q & 31))
//   Phase A STS.128: lane l writes f4=l  -> banks l^(q&31), all distinct.
//   Phase B LDS.128: lane l reads q=32k+l, f4=c4 -> banks c4^l, all distinct.
// Phase B emits 4 coalesced 128B STG.32 streams (evict-first via __stcs).
// ---------------------------------------------------------------------------
__global__ __launch_bounds__(256) void gather_kernel(float* __restrict__ out)
{
    __shared__ float4 sm4[64 * 32];     // 32 KB
    const int tid = threadIdx.x;
    const int w = tid >> 5, l = tid & 31;
    const int q0 = blockIdx.x * 64;

    const unsigned long long pol = policy_evict_last();
    const float4* scr4 = (const float4*)g_scratch;

#pragma unroll
    for (int i = 0; i < 8; i++) {
        const int q = w * 8 + i;                 // local query 0..63
        const int p = __ldg(&g_idx[q0 + q]);     // broadcast
        float4 v = make_float4(0.f, 0.f, 0.f, 0.f);
        if (p >= 0)
            v = ldg_el4(scr4 + (size_t)p * 32 + l, pol);
        sm4[q * 32 + (l ^ (q & 31))] = v;
    }
    __syncthreads();

#pragma unroll
    for (int j = 0; j < 4; j++) {
        const int c4 = w * 4 + j;                // float4 channel group 0..31
#pragma unroll
        for (int k = 0; k < 2; k++) {
            const int q = 32 * k + l;
            float4 v = sm4[q * 32 + (c4 ^ l)];   // (q & 31) == l
            const size_t gq = (size_t)q0 + q;
            __stcs(&out[(size_t)(4 * c4 + 0) * NQ + gq], v.x);
            __stcs(&out[(size_t)(4 * c4 + 1) * NQ + gq], v.y);
            __stcs(&out[(size_t)(4 * c4 + 2) * NQ + gq], v.z);
            __stcs(&out[(size_t)(4 * c4 + 3) * NQ + gq], v.w);
        }
    }
}

// ---------------------------------------------------------------------------
extern "C" void kernel_launch(void* const* d_in, const int* in_sizes, int n_in,
                              void* d_out, int out_size) {
    const float* img   = (const float*)d_in[0];   // (6,128,64,176) f32
    const float* pts   = (const float*)d_in[1];   // (6,640000,2)  f32
    const void*  valid = d_in[2];                 // (6,640000) bool-ish
    float*       out   = (float*)d_out;           // (128,200,200,16) f32

    index_kernel<<<NQ / 256, 256>>>(pts, valid);

    dim3 tb(32, 8);
    dim3 tg(HW / 32, C_CH / 32, N_CAM);           // (352, 4, 6)
    transpose_kernel<<<tg, tb>>>(img);

    gather_kernel<<<NQ / 64, 256>>>(out);
}

// round 5
// speedup vs baseline: 1.6438x; 1.0215x over previous
#include <cuda_runtime.h>
#include <cstdint>
#include <cstddef>

#define N_CAM 6
#define C_CH  128
#define H_IMG 64
#define W_IMG 176
#define HW    (H_IMG * W_IMG)     // 11264
#define NQ    640000              // 200*200*16

#define T_BLOCKS ((HW / 32) * (C_CH / 32) * N_CAM)   // 8448 transpose blocks
#define I_BLOCKS (NQ / 256)                          // 2500 index blocks

// Scratch: img_feats transposed to (cam, h, w, c): query's 128 channels are
// 512 contiguous bytes. 34.6 MB static __device__ (alloc-free).
__device__ float g_scratch[(size_t)N_CAM * HW * C_CH];
// Per-query packed spatial index into scratch (element-row index), -1 invalid.
__device__ int g_idx[NQ];

// ---- cache-hinted accessors (createpolicy + L2::cache_hint) ----------------
__device__ __forceinline__ unsigned long long policy_evict_last() {
    unsigned long long p;
    asm("createpolicy.fractional.L2::evict_last.b64 %0, 1.0;" : "=l"(p));
    return p;
}
__device__ __forceinline__ void stg_el(float* ptr, float v, unsigned long long pol) {
    asm volatile("st.global.L2::cache_hint.f32 [%0], %1, %2;"
                 :: "l"(ptr), "f"(v), "l"(pol));
}
__device__ __forceinline__ float4 ldg_el4(const float4* ptr, unsigned long long pol) {
    float4 v;
    asm volatile("ld.global.L2::cache_hint.v4.f32 {%0,%1,%2,%3}, [%4], %5;"
                 : "=f"(v.x), "=f"(v.y), "=f"(v.z), "=f"(v.w)
                 : "l"(ptr), "l"(pol));
    return v;
}

// ---------------------------------------------------------------------------
// Fused prologue: one launch, block-role split so the transpose (DRAM-read
// bound, ~12us) and the index precompute (~11.5us) overlap across SMs instead
// of serializing. Both must finish before gather_kernel.
//
// Role A (bid < T_BLOCKS): tiled transpose (C,HW)->(HW,C) per cam; streaming
//   reads, scratch writes pinned in L2 (evict_last) for the gather's re-reads.
// Role B: per-query cam-select + round-to-nearest-even (== jnp.round) into
//   g_idx. Valid dtype detected per block: a 1-byte bool array has ~30%
//   nonzero bytes at offsets ≡ 1 (mod 4); int32/f32 encodings of 0/1 have
//   0x00 there. 1024 samples -> P(false negative) ~ 0.7^1024.
// ---------------------------------------------------------------------------
__global__ __launch_bounds__(256) void prologue_kernel(
    const float* __restrict__ img,
    const float* __restrict__ pts,
    const void*  __restrict__ valid)
{
    const int tid = threadIdx.x;

    if (blockIdx.x < T_BLOCKS) {
        // ---- transpose role ----
        __shared__ float tile[32][33];
        int bid = blockIdx.x;
        const int cam = bid / ((HW / 32) * (C_CH / 32));
        bid -= cam * ((HW / 32) * (C_CH / 32));
        const int cb  = bid / (HW / 32);
        const int hwb = bid - cb * (HW / 32);
        const int hw0 = hwb * 32;
        const int c0  = cb * 32;
        const int tx = tid & 31, ty = tid >> 5;     // 32 x 8

        const unsigned long long pol = policy_evict_last();
        const float* src = img + (size_t)cam * C_CH * HW;
        float*       dst = g_scratch + (size_t)cam * HW * C_CH;

#pragma unroll
        for (int k = 0; k < 4; k++) {
            int c = c0 + ty + k * 8;
            tile[ty + k * 8][tx] = __ldcs(&src[(size_t)c * HW + hw0 + tx]);
        }
        __syncthreads();
#pragma unroll
        for (int k = 0; k < 4; k++) {
            int hw = hw0 + ty + k * 8;
            stg_el(&dst[(size_t)hw * C_CH + c0 + tx], tile[tx][ty + k * 8], pol);
        }
    } else {
        // ---- index role ----
        const int q = (blockIdx.x - T_BLOCKS) * 256 + tid;
        const unsigned char* vb = (const unsigned char*)valid;
        const unsigned int*  vw = (const unsigned int*)valid;

        int found = 0;
#pragma unroll
        for (int j = 0; j < 4; j++)
            if (vb[1 + 4 * (tid * 4 + j)] != 0) found = 1;
        const int isByte = __syncthreads_or(found);

        int cam = -1;
        if (isByte) {
#pragma unroll
            for (int cc = 0; cc < N_CAM; cc++)
                if (vb[(size_t)cc * NQ + q] != 0) cam = cc;
        } else {
#pragma unroll
            for (int cc = 0; cc < N_CAM; cc++)
                if (vw[(size_t)cc * NQ + q] != 0u) cam = cc;
        }

        int p = -1;
        if (cam >= 0) {
            float2 pt = ((const float2*)pts)[(size_t)cam * NQ + q];
            int x = min(max(__float2int_rn(pt.x), 0), W_IMG - 1);
            int y = min(max(__float2int_rn(pt.y), 0), H_IMG - 1);
            p = cam * HW + y * W_IMG + x;
        }
        g_idx[q] = p;
    }
}

// ---------------------------------------------------------------------------
// Gather: tile = 64 queries x 128 channels, 32KB smem, all 128-bit accesses.
// XOR-swizzled float4 layout: slot(q, f4) = q*32 + (f4 ^ (q & 31))
//   Phase A STS.128: lane l writes f4=l  -> banks l^(q&31), all distinct.
//   Phase B LDS.128: lane l reads q=32k+l, f4=c4 -> banks c4^l, all distinct.
// Phase B emits 4 coalesced 128B STG.32 streams (evict-first via __stcs).
// ---------------------------------------------------------------------------
__global__ __launch_bounds__(256) void gather_kernel(float* __restrict__ out)
{
    __shared__ float4 sm4[64 * 32];     // 32 KB
    const int tid = threadIdx.x;
    const int w = tid >> 5, l = tid & 31;
    const int q0 = blockIdx.x * 64;

    const unsigned long long pol = policy_evict_last();
    const float4* scr4 = (const float4*)g_scratch;

#pragma unroll
    for (int i = 0; i < 8; i++) {
        const int q = w * 8 + i;                 // local query 0..63
        const int p = __ldg(&g_idx[q0 + q]);     // broadcast
        float4 v = make_float4(0.f, 0.f, 0.f, 0.f);
        if (p >= 0)
            v = ldg_el4(scr4 + (size_t)p * 32 + l, pol);
        sm4[q * 32 + (l ^ (q & 31))] = v;
    }
    __syncthreads();

#pragma unroll
    for (int j = 0; j < 4; j++) {
        const int c4 = w * 4 + j;                // float4 channel group 0..31
#pragma unroll
        for (int k = 0; k < 2; k++) {
            const int q = 32 * k + l;
            float4 v = sm4[q * 32 + (c4 ^ l)];   // (q & 31) == l
            const size_t gq = (size_t)q0 + q;
            __stcs(&out[(size_t)(4 * c4 + 0) * NQ + gq], v.x);
            __stcs(&out[(size_t)(4 * c4 + 1) * NQ + gq], v.y);
            __stcs(&out[(size_t)(4 * c4 + 2) * NQ + gq], v.z);
            __stcs(&out[(size_t)(4 * c4 + 3) * NQ + gq], v.w);
        }
    }
}

// ---------------------------------------------------------------------------
extern "C" void kernel_launch(void* const* d_in, const int* in_sizes, int n_in,
                              void* d_out, int out_size) {
    const float* img   = (const float*)d_in[0];   // (6,128,64,176) f32
    const float* pts   = (const float*)d_in[1];   // (6,640000,2)  f32
    const void*  valid = d_in[2];                 // (6,640000) bool-ish
    float*       out   = (float*)d_out;           // (128,200,200,16) f32

    prologue_kernel<<<T_BLOCKS + I_BLOCKS, 256>>>(img, pts, valid);
    gather_kernel<<<NQ / 64, 256>>>(out);
}

// round 6
// speedup vs baseline: 1.7958x; 1.0925x over previous
#include <cuda_runtime.h>
#include <cstdint>
#include <cstddef>

#define N_CAM 6
#define C_CH  128
#define H_IMG 64
#define W_IMG 176
#define HW    (H_IMG * W_IMG)     // 11264
#define NQ    640000              // 200*200*16

#define T_BLOCKS ((HW / 32) * (C_CH / 32) * N_CAM)   // 8448 transpose blocks
#define I_BLOCKS (NQ / 256)                          // 2500 index blocks

// Scratch: img_feats transposed to (cam, h, w, c): query's 128 channels are
// 512 contiguous bytes. 34.6 MB static __device__ (alloc-free).
__device__ float g_scratch[(size_t)N_CAM * HW * C_CH];
// Per-query packed spatial index into scratch (element-row index), -1 invalid.
__device__ int g_idx[NQ];

// ---- cache-hinted accessors (createpolicy + L2::cache_hint) ----------------
__device__ __forceinline__ unsigned long long policy_evict_last() {
    unsigned long long p;
    asm("createpolicy.fractional.L2::evict_last.b64 %0, 1.0;" : "=l"(p));
    return p;
}
__device__ __forceinline__ void stg_el(float* ptr, float v, unsigned long long pol) {
    asm volatile("st.global.L2::cache_hint.f32 [%0], %1, %2;"
                 :: "l"(ptr), "f"(v), "l"(pol));
}

// ---------------------------------------------------------------------------
// Fused prologue: one launch, block-role split (transpose overlaps index).
// Role A (bid < T_BLOCKS): tiled transpose (C,HW)->(HW,C) per cam; streaming
//   reads, scratch writes pinned in L2 (evict_last) for the gather's re-reads.
// Role B: per-query cam-select + round-to-nearest-even (== jnp.round) into
//   g_idx. Valid dtype detected per block: a 1-byte bool array has ~30%
//   nonzero bytes at offsets ≡ 1 (mod 4); int32/f32 encodings of 0/1 have
//   0x00 there. 1024 samples -> P(false negative) ~ 0.7^1024.
// ---------------------------------------------------------------------------
__global__ __launch_bounds__(256) void prologue_kernel(
    const float* __restrict__ img,
    const float* __restrict__ pts,
    const void*  __restrict__ valid)
{
    const int tid = threadIdx.x;

    if (blockIdx.x < T_BLOCKS) {
        // ---- transpose role ----
        __shared__ float tile[32][33];
        int bid = blockIdx.x;
        const int cam = bid / ((HW / 32) * (C_CH / 32));
        bid -= cam * ((HW / 32) * (C_CH / 32));
        const int cb  = bid / (HW / 32);
        const int hwb = bid - cb * (HW / 32);
        const int hw0 = hwb * 32;
        const int c0  = cb * 32;
        const int tx = tid & 31, ty = tid >> 5;     // 32 x 8

        const unsigned long long pol = policy_evict_last();
        const float* src = img + (size_t)cam * C_CH * HW;
        float*       dst = g_scratch + (size_t)cam * HW * C_CH;

#pragma unroll
        for (int k = 0; k < 4; k++) {
            int c = c0 + ty + k * 8;
            tile[ty + k * 8][tx] = __ldcs(&src[(size_t)c * HW + hw0 + tx]);
        }
        __syncthreads();
#pragma unroll
        for (int k = 0; k < 4; k++) {
            int hw = hw0 + ty + k * 8;
            stg_el(&dst[(size_t)hw * C_CH + c0 + tx], tile[tx][ty + k * 8], pol);
        }
    } else {
        // ---- index role ----
        const int q = (blockIdx.x - T_BLOCKS) * 256 + tid;
        const unsigned char* vb = (const unsigned char*)valid;
        const unsigned int*  vw = (const unsigned int*)valid;

        int found = 0;
#pragma unroll
        for (int j = 0; j < 4; j++)
            if (vb[1 + 4 * (tid * 4 + j)] != 0) found = 1;
        const int isByte = __syncthreads_or(found);

        int cam = -1;
        if (isByte) {
#pragma unroll
            for (int cc = 0; cc < N_CAM; cc++)
                if (vb[(size_t)cc * NQ + q] != 0) cam = cc;
        } else {
#pragma unroll
            for (int cc = 0; cc < N_CAM; cc++)
                if (vw[(size_t)cc * NQ + q] != 0u) cam = cc;
        }

        int p = -1;
        if (cam >= 0) {
            float2 pt = ((const float2*)pts)[(size_t)cam * NQ + q];
            int x = min(max(__float2int_rn(pt.x), 0), W_IMG - 1);
            int y = min(max(__float2int_rn(pt.y), 0), H_IMG - 1);
            p = cam * HW + y * W_IMG + x;
        }
        g_idx[q] = p;
    }
}

// ---------------------------------------------------------------------------
// Gather: tile = 64 queries x 128 channels, 32KB smem, all 128-bit accesses.
// XOR-swizzled float4 layout: slot(q, f4) = q*32 + (f4 ^ (q & 31))
// Phase A: cp.async.cg (L2->smem direct, no register landing, latency held in
//   the HW queue). Invalid queries zero-fill via the src-size=0 operand.
//   Idx values preloaded by 8 lanes (one 32B coalesced load) + shuffle.
// Phase B: conflict-free LDS.128 + 4 coalesced 128B STG.32 streams (__stcs,
//   evict-first so the 328MB output stream never evicts the L2 scratch).
// ---------------------------------------------------------------------------
__global__ __launch_bounds__(256) void gather_kernel(float* __restrict__ out)
{
    __shared__ float4 sm4[64 * 32];     // 32 KB
    const int tid = threadIdx.x;
    const int w = tid >> 5, l = tid & 31;
    const int q0 = blockIdx.x * 64;

    const unsigned long long pol = policy_evict_last();
    const float4* scr4 = (const float4*)g_scratch;

    // Preload this warp's 8 query indices (lanes 0..7, coalesced 32B).
    int pv = 0;
    if (l < 8) pv = g_idx[q0 + w * 8 + l];

    const unsigned int smem_base =
        (unsigned int)__cvta_generic_to_shared(sm4);

#pragma unroll
    for (int i = 0; i < 8; i++) {
        const int p = __shfl_sync(0xffffffffu, pv, i);
        const int q = w * 8 + i;                 // local query 0..63
        const unsigned int dst =
            smem_base + (unsigned int)((q * 32 + (l ^ (q & 31))) * 16);
        const float4* src = scr4 + (size_t)max(p, 0) * 32 + l;
        const int sz = (p >= 0) ? 16 : 0;        // 0 -> 16B zero-fill
        asm volatile(
            "cp.async.cg.shared.global.L2::cache_hint [%0], [%1], 16, %2, %3;"
            :: "r"(dst), "l"(src), "r"(sz), "l"(pol) : "memory");
    }
    asm volatile("cp.async.commit_group;" ::: "memory");
    asm volatile("cp.async.wait_group 0;" ::: "memory");
    __syncthreads();

#pragma unroll
    for (int j = 0; j < 4; j++) {
        const int c4 = w * 4 + j;                // float4 channel group 0..31
#pragma unroll
        for (int k = 0; k < 2; k++) {
            const int q = 32 * k + l;
            float4 v = sm4[q * 32 + (c4 ^ l)];   // (q & 31) == l
            const size_t gq = (size_t)q0 + q;
            __stcs(&out[(size_t)(4 * c4 + 0) * NQ + gq], v.x);
            __stcs(&out[(size_t)(4 * c4 + 1) * NQ + gq], v.y);
            __stcs(&out[(size_t)(4 * c4 + 2) * NQ + gq], v.z);
            __stcs(&out[(size_t)(4 * c4 + 3) * NQ + gq], v.w);
        }
    }
}

// ---------------------------------------------------------------------------
extern "C" void kernel_launch(void* const* d_in, const int* in_sizes, int n_in,
                              void* d_out, int out_size) {
    const float* img   = (const float*)d_in[0];   // (6,128,64,176) f32
    const float* pts   = (const float*)d_in[1];   // (6,640000,2)  f32
    const void*  valid = d_in[2];                 // (6,640000) bool-ish
    float*       out   = (float*)d_out;           // (128,200,200,16) f32

    prologue_kernel<<<T_BLOCKS + I_BLOCKS, 256>>>(img, pts, valid);
    gather_kernel<<<NQ / 64, 256>>>(out);
}

// round 7
// speedup vs baseline: 1.8672x; 1.0398x over previous
#include <cuda_runtime.h>
#include <cstdint>
#include <cstddef>

#define N_CAM 6
#define C_CH  128
#define H_IMG 64
#define W_IMG 176
#define HW    (H_IMG * W_IMG)     // 11264
#define NQ    640000              // 200*200*16

#define T_BLOCKS ((HW / 32) * (C_CH / 32) * N_CAM)   // 8448 transpose blocks
#define I_BLOCKS (NQ / 256)                          // 2500 index blocks
#define P_BLOCKS (T_BLOCKS + I_BLOCKS)               // 10948
// Interleave: for bid < 4*I_BLOCKS, every 4th block (bid%4==3) is an index
// block; the rest (and everything above) are transpose blocks. This makes the
// two roles co-resident from wave 0 instead of running back-to-back.
#define I_SPAN (4 * I_BLOCKS)                        // 10000

// Scratch: img_feats transposed to (cam, h, w, c): query's 128 channels are
// 512 contiguous bytes. 34.6 MB static __device__ (alloc-free).
__device__ float g_scratch[(size_t)N_CAM * HW * C_CH];
// Per-query packed spatial index into scratch (element-row index), -1 invalid.
__device__ int g_idx[NQ];

// ---- cache-hinted accessors (createpolicy + L2::cache_hint) ----------------
__device__ __forceinline__ unsigned long long policy_evict_last() {
    unsigned long long p;
    asm("createpolicy.fractional.L2::evict_last.b64 %0, 1.0;" : "=l"(p));
    return p;
}
__device__ __forceinline__ void stg_el(float* ptr, float v, unsigned long long pol) {
    asm volatile("st.global.L2::cache_hint.f32 [%0], %1, %2;"
                 :: "l"(ptr), "f"(v), "l"(pol));
}

// ---------------------------------------------------------------------------
// Fused prologue, role-interleaved.
// Role A: tiled transpose (C,HW)->(HW,C) per cam; streaming reads, scratch
//   writes pinned in L2 (evict_last) for the gather's re-reads.
// Role B: per-query cam-select + round-to-nearest-even (== jnp.round) into
//   g_idx. All 6 cams' points are prefetched unconditionally (independent
//   loads, MLP=6) so the select never waits on a dependent load.
//   Valid dtype detected per block: a 1-byte bool array has ~30% nonzero
//   bytes at offsets ≡ 1 (mod 4); int32/f32 encodings of 0/1 have 0x00 there.
//   1024 samples -> P(false negative) ~ 0.7^1024.
// ---------------------------------------------------------------------------
__global__ __launch_bounds__(256) void prologue_kernel(
    const float* __restrict__ img,
    const float* __restrict__ pts,
    const void*  __restrict__ valid)
{
    const int tid = threadIdx.x;
    const int bid = blockIdx.x;
    const bool is_index = (bid < I_SPAN) && ((bid & 3) == 3);

    if (!is_index) {
        // ---- transpose role ----
        const int t_id = (bid < I_SPAN) ? (bid - ((bid + 1) >> 2))
                                        : (bid - I_BLOCKS);
        __shared__ float tile[32][33];
        int b = t_id;
        const int cam = b / ((HW / 32) * (C_CH / 32));
        b -= cam * ((HW / 32) * (C_CH / 32));
        const int cb  = b / (HW / 32);
        const int hwb = b - cb * (HW / 32);
        const int hw0 = hwb * 32;
        const int c0  = cb * 32;
        const int tx = tid & 31, ty = tid >> 5;     // 32 x 8

        const unsigned long long pol = policy_evict_last();
        const float* src = img + (size_t)cam * C_CH * HW;
        float*       dst = g_scratch + (size_t)cam * HW * C_CH;

#pragma unroll
        for (int k = 0; k < 4; k++) {
            int c = c0 + ty + k * 8;
            tile[ty + k * 8][tx] = __ldcs(&src[(size_t)c * HW + hw0 + tx]);
        }
        __syncthreads();
#pragma unroll
        for (int k = 0; k < 4; k++) {
            int hw = hw0 + ty + k * 8;
            stg_el(&dst[(size_t)hw * C_CH + c0 + tx], tile[tx][ty + k * 8], pol);
        }
    } else {
        // ---- index role ----
        const int q = (bid >> 2) * 256 + tid;
        const unsigned char* vb = (const unsigned char*)valid;
        const unsigned int*  vw = (const unsigned int*)valid;

        int found = 0;
#pragma unroll
        for (int j = 0; j < 4; j++)
            if (vb[1 + 4 * (tid * 4 + j)] != 0) found = 1;
        const int isByte = __syncthreads_or(found);

        // Prefetch all 6 cams' points (independent, MLP=6) before the select.
        float2 pt[N_CAM];
#pragma unroll
        for (int cc = 0; cc < N_CAM; cc++)
            pt[cc] = __ldg(&((const float2*)pts)[(size_t)cc * NQ + q]);

        int cam = -1;
        if (isByte) {
#pragma unroll
            for (int cc = 0; cc < N_CAM; cc++)
                if (vb[(size_t)cc * NQ + q] != 0) cam = cc;
        } else {
#pragma unroll
            for (int cc = 0; cc < N_CAM; cc++)
                if (vw[(size_t)cc * NQ + q] != 0u) cam = cc;
        }

        int p = -1;
        if (cam >= 0) {
            float2 sp = pt[cam];
            int x = min(max(__float2int_rn(sp.x), 0), W_IMG - 1);
            int y = min(max(__float2int_rn(sp.y), 0), H_IMG - 1);
            p = cam * HW + y * W_IMG + x;
        }
        g_idx[q] = p;
    }
}

// ---------------------------------------------------------------------------
// Gather: tile = 64 queries x 128 channels, 32KB smem, all 128-bit accesses.
// XOR-swizzled float4 layout: slot(q, f4) = q*32 + (f4 ^ (q & 31))
// Phase A: cp.async.cg (L2->smem direct, latency held in the HW queue);
//   invalid queries zero-fill via the src-size=0 operand; idx preloaded by
//   8 lanes (one 32B coalesced load) + shuffle.
// Phase B: conflict-free LDS.128 + 4 coalesced 128B STG.32 streams (__stcs,
//   evict-first so the 328MB output stream never evicts the L2 scratch).
// ---------------------------------------------------------------------------
__global__ __launch_bounds__(256) void gather_kernel(float* __restrict__ out)
{
    __shared__ float4 sm4[64 * 32];     // 32 KB
    const int tid = threadIdx.x;
    const int w = tid >> 5, l = tid & 31;
    const int q0 = blockIdx.x * 64;

    const unsigned long long pol = policy_evict_last();
    const float4* scr4 = (const float4*)g_scratch;

    int pv = 0;
    if (l < 8) pv = g_idx[q0 + w * 8 + l];

    const unsigned int smem_base =
        (unsigned int)__cvta_generic_to_shared(sm4);

#pragma unroll
    for (int i = 0; i < 8; i++) {
        const int p = __shfl_sync(0xffffffffu, pv, i);
        const int q = w * 8 + i;                 // local query 0..63
        const unsigned int dst =
            smem_base + (unsigned int)((q * 32 + (l ^ (q & 31))) * 16);
        const float4* src = scr4 + (size_t)max(p, 0) * 32 + l;
        const int sz = (p >= 0) ? 16 : 0;        // 0 -> 16B zero-fill
        asm volatile(
            "cp.async.cg.shared.global.L2::cache_hint [%0], [%1], 16, %2, %3;"
            :: "r"(dst), "l"(src), "r"(sz), "l"(pol) : "memory");
    }
    asm volatile("cp.async.commit_group;" ::: "memory");
    asm volatile("cp.async.wait_group 0;" ::: "memory");
    __syncthreads();

#pragma unroll
    for (int j = 0; j < 4; j++) {
        const int c4 = w * 4 + j;                // float4 channel group 0..31
#pragma unroll
        for (int k = 0; k < 2; k++) {
            const int q = 32 * k + l;
            float4 v = sm4[q * 32 + (c4 ^ l)];   // (q & 31) == l
            const size_t gq = (size_t)q0 + q;
            __stcs(&out[(size_t)(4 * c4 + 0) * NQ + gq], v.x);
            __stcs(&out[(size_t)(4 * c4 + 1) * NQ + gq], v.y);
            __stcs(&out[(size_t)(4 * c4 + 2) * NQ + gq], v.z);
            __stcs(&out[(size_t)(4 * c4 + 3) * NQ + gq], v.w);
        }
    }
}

// ---------------------------------------------------------------------------
extern "C" void kernel_launch(void* const* d_in, const int* in_sizes, int n_in,
                              void* d_out, int out_size) {
    const float* img   = (const float*)d_in[0];   // (6,128,64,176) f32
    const float* pts   = (const float*)d_in[1];   // (6,640000,2)  f32
    const void*  valid = d_in[2];                 // (6,640000) bool-ish
    float*       out   = (float*)d_out;           // (128,200,200,16) f32

    prologue_kernel<<<P_BLOCKS, 256>>>(img, pts, valid);
    gather_kernel<<<NQ / 64, 256>>>(out);
}